// round 5
// baseline (speedup 1.0000x reference)
#include <cuda_runtime.h>
#include <mma.h>
#include <math.h>

using namespace nvcuda;

// Problem constants
#define BB 4
#define NN 8192
#define DD 1024
#define HH 16
#define DHH 64
#define GHH 256
#define ROWS (BB*HH)          // 64
#define NSPLIT 64

// ---------------- scratch (static device allocations only) ----------------
__device__ float g_part[NSPLIT * BB * DD];
__device__ float g_xbar[BB * DD];
__device__ float g_barq[BB * DD];
__device__ float g_h1[ROWS * GHH];
__device__ float g_h2[ROWS * GHH];
__device__ float g_gbuf[ROWS * 2 * NN];             // re | im
__device__ float g_sbuf[ROWS * NN];
__device__ float g_vbuf[(size_t)BB * DD * NN];      // [b][c][n]

__device__ __forceinline__ float gelu_exact(float x) {
    return 0.5f * x * (1.0f + erff(x * 0.70710678118654752440f));
}

// -------- cp.async helpers --------
__device__ __forceinline__ void cp_async16(void* smem_dst, const void* gmem_src) {
    unsigned s = (unsigned)__cvta_generic_to_shared(smem_dst);
    asm volatile("cp.async.cg.shared.global [%0], [%1], 16;\n" :: "r"(s), "l"(gmem_src));
}
__device__ __forceinline__ void cp_commit() {
    asm volatile("cp.async.commit_group;\n");
}
__device__ __forceinline__ void cp_wait1() {
    asm volatile("cp.async.wait_group 1;\n");
}
__device__ __forceinline__ void cp_wait0() {
    asm volatile("cp.async.wait_group 0;\n");
}

// ---------------- 1) xbar = mean_n x ----------------
__global__ void k_xbar_part(const float* __restrict__ x) {
    int s = blockIdx.x, b = blockIdx.y, tid = threadIdx.x;
    float acc[4] = {0.f, 0.f, 0.f, 0.f};
    const float* xp = x + ((size_t)b * NN + (size_t)s * (NN / NSPLIT)) * DD;
    for (int n = 0; n < NN / NSPLIT; n++) {
#pragma unroll
        for (int i = 0; i < 4; i++) acc[i] += xp[(size_t)n * DD + tid + 256 * i];
    }
#pragma unroll
    for (int i = 0; i < 4; i++)
        g_part[((size_t)s * BB + b) * DD + tid + 256 * i] = acc[i];
}

__global__ void k_xbar_red() {
    int b = blockIdx.x, tid = threadIdx.x;
    for (int d = tid; d < DD; d += 256) {
        float a = 0.f;
        for (int s = 0; s < NSPLIT; s++) a += g_part[((size_t)s * BB + b) * DD + d];
        g_xbar[b * DD + d] = a * (1.0f / NN);
    }
}

// ---------------- 2) bar_q = xbar @ w_q ----------------
__global__ void k_barq(const float* __restrict__ wq) {
    __shared__ float xb[DD];
    int b = blockIdx.y, tid = threadIdx.x;
    for (int l = tid; l < DD; l += 256) xb[l] = g_xbar[b * DD + l];
    __syncthreads();
    int c = blockIdx.x * 256 + tid;
    float acc = 0.f;
    for (int d = 0; d < DD; d++) acc += xb[d] * wq[(size_t)d * DD + c];
    g_barq[b * DD + c] = acc;
}

// ---------------- 3) LayerNorm + tiny MLP first layers ----------------
__global__ void k_ln_mlp(const float* __restrict__ ln_g, const float* __restrict__ ln_b,
                         const float* __restrict__ gate_w1, const float* __restrict__ wrm_w1) {
    __shared__ float q[DHH];
    __shared__ float qn[DHH];
    __shared__ float stats[2];
    int r = blockIdx.x;
    int b = r / HH, c0 = (r % HH) * DHH;
    int tid = threadIdx.x;
    if (tid < DHH) q[tid] = g_barq[b * DD + c0 + tid];
    __syncthreads();
    if (tid == 0) {
        float mu = 0.f;
        for (int i = 0; i < DHH; i++) mu += q[i];
        mu *= (1.0f / DHH);
        float var = 0.f;
        for (int i = 0; i < DHH; i++) { float t = q[i] - mu; var += t * t; }
        var *= (1.0f / DHH);
        stats[0] = mu; stats[1] = rsqrtf(var + 1e-5f);
    }
    __syncthreads();
    if (tid < DHH) qn[tid] = (q[tid] - stats[0]) * stats[1] * ln_g[tid] + ln_b[tid];
    __syncthreads();
    float a1 = 0.f, a2 = 0.f;
    for (int dh = 0; dh < DHH; dh++) {
        float qv = qn[dh];
        a1 += qv * gate_w1[dh * GHH + tid];
        a2 += qv * wrm_w1[dh * GHH + tid];
    }
    g_h1[r * GHH + tid] = gelu_exact(a1);
    g_h2[r * GHH + tid] = gelu_exact(a2);
}

// ---------------- 4) g = h1 @ gate_w2 ; s = h2 @ wrm_w2 ----------------
__global__ void k_gs(const float* __restrict__ w2, int width, int which) {
    __shared__ float sh[16][GHH];
    const float* hb = which ? g_h2 : g_h1;
    float* op = which ? g_sbuf : g_gbuf;
    int r0 = blockIdx.y * 16;
    int tid = threadIdx.x;
    for (int l = tid; l < 16 * GHH; l += 256)
        sh[l >> 8][l & 255] = hb[(r0 + (l >> 8)) * GHH + (l & 255)];
    __syncthreads();
    int c = blockIdx.x * 256 + tid;
    float acc[16];
#pragma unroll
    for (int r = 0; r < 16; r++) acc[r] = 0.f;
    for (int j = 0; j < GHH; j++) {
        float w = w2[(size_t)j * width + c];
#pragma unroll
        for (int r = 0; r < 16; r++) acc[r] += sh[r][j] * w;
    }
#pragma unroll
    for (int r = 0; r < 16; r++) op[(size_t)(r0 + r) * width + c] = acc[r];
}

// ================= pipelined tf32 tensor-core GEMMs =================
// Tile 128x128x32, cp.async double-buffered, 8 warps (2x4), warp tile 64x32.
#define BKX 32
#define NKT (DD / BKX)          // 16... wait DD=1024 -> 32 k-tiles
#define LDAX 132                // padded ld for 128-wide tiles
#define LDBV 36                 // padded ld for 32-deep B (v-GEMM)

// sizes in floats
#define AV_F (BKX * LDAX)       // 32*132 = 4224
#define BV_F (128 * LDBV)       // 128*36 = 4608
#define STG_V (AV_F + BV_F)     // 8832 floats = 35328 B
#define AO_F (BKX * LDAX)
#define BO_F (BKX * LDAX)
#define STG_O (AO_F + BO_F)     // 8448 floats = 33792 B

// ---------------- 5) v = x @ w_v -> g_vbuf[b][c][n] ----------------
// C[c][n] = sum_d wv[d][c] * x[n][d]
__global__ __launch_bounds__(256) void k_gemm_v_tc(const float* __restrict__ x,
                                                   const float* __restrict__ wv) {
    extern __shared__ __align__(16) float smv[];
    int b = blockIdx.z;
    int c0 = blockIdx.x * 128;     // c-tile fastest: 8 CTAs share x block in L2
    int n0 = blockIdx.y * 128;
    int tid = threadIdx.x;
    int warp = tid >> 5;
    int wm = (warp & 1) * 64;      // c offset
    int wn = (warp >> 1) * 32;     // n offset
    const float* xb = x + (size_t)b * NN * DD;

    wmma::fragment<wmma::accumulator, 16, 16, 8, float> acc[4][2];
#pragma unroll
    for (int i = 0; i < 4; i++)
#pragma unroll
        for (int j = 0; j < 2; j++) wmma::fill_fragment(acc[i][j], 0.0f);

    // per-thread load coords (4 x float4 each for A and B)
    int ad[4], ac4[4], bn[4], bd4[4];
#pragma unroll
    for (int i = 0; i < 4; i++) {
        int f = tid + 256 * i;
        ad[i] = f >> 5;  ac4[i] = f & 31;    // A: 32 d-rows x 32 float4 of c
        bn[i] = f >> 3;  bd4[i] = f & 7;     // B: 128 n-rows x 8 float4 of d
    }

#define LOAD_V_TILE(kt, buf) do {                                              \
        float* As_ = smv + (buf) * STG_V;                                      \
        float* Bs_ = As_ + AV_F;                                               \
        int k0_ = (kt) * BKX;                                                  \
        _Pragma("unroll")                                                      \
        for (int i = 0; i < 4; i++)                                            \
            cp_async16(&As_[ad[i] * LDAX + ac4[i] * 4],                        \
                       wv + (size_t)(k0_ + ad[i]) * DD + c0 + ac4[i] * 4);     \
        _Pragma("unroll")                                                      \
        for (int i = 0; i < 4; i++)                                            \
            cp_async16(&Bs_[bn[i] * LDBV + bd4[i] * 4],                        \
                       xb + (size_t)(n0 + bn[i]) * DD + k0_ + bd4[i] * 4);     \
        cp_commit();                                                           \
    } while (0)

    LOAD_V_TILE(0, 0);
    for (int kt = 0; kt < DD / BKX; kt++) {
        int buf = kt & 1;
        if (kt + 1 < DD / BKX) { LOAD_V_TILE(kt + 1, buf ^ 1); cp_wait1(); }
        else cp_wait0();
        __syncthreads();
        float* As_ = smv + buf * STG_V;
        float* Bs_ = As_ + AV_F;
#pragma unroll
        for (int kk = 0; kk < BKX; kk += 8) {
            wmma::fragment<wmma::matrix_a, 16, 16, 8, wmma::precision::tf32, wmma::col_major> af[4];
            wmma::fragment<wmma::matrix_b, 16, 16, 8, wmma::precision::tf32, wmma::col_major> bf[2];
#pragma unroll
            for (int i = 0; i < 4; i++) {
                wmma::load_matrix_sync(af[i], As_ + kk * LDAX + wm + 16 * i, LDAX);
#pragma unroll
                for (int t = 0; t < af[i].num_elements; t++)
                    af[i].x[t] = wmma::__float_to_tf32(af[i].x[t]);
            }
#pragma unroll
            for (int j = 0; j < 2; j++) {
                wmma::load_matrix_sync(bf[j], Bs_ + (wn + 16 * j) * LDBV + kk, LDBV);
#pragma unroll
                for (int t = 0; t < bf[j].num_elements; t++)
                    bf[j].x[t] = wmma::__float_to_tf32(bf[j].x[t]);
            }
#pragma unroll
            for (int i = 0; i < 4; i++)
#pragma unroll
                for (int j = 0; j < 2; j++)
                    wmma::mma_sync(acc[i][j], af[i], bf[j], acc[i][j]);
        }
        __syncthreads();
    }
#pragma unroll
    for (int i = 0; i < 4; i++)
#pragma unroll
        for (int j = 0; j < 2; j++) {
            float* cp = g_vbuf + ((size_t)b * DD + c0 + wm + 16 * i) * NN + n0 + wn + 16 * j;
            wmma::store_matrix_sync(cp, acc[i][j], NN, wmma::mem_row_major);
        }
}

// ---------------- 7) out = y @ w_o  (y[b][m][d] = g_vbuf[b][d][m]) ----------------
// C[m][c'] = sum_d vbuf[d][m] * wo[d][c']
__global__ __launch_bounds__(256) void k_gemm_o_tc(const float* __restrict__ wo,
                                                   float* __restrict__ outp) {
    extern __shared__ __align__(16) float smo[];
    int b = blockIdx.z;
    int c0 = blockIdx.x * 128;     // c'-tile fastest
    int m0 = blockIdx.y * 128;
    int tid = threadIdx.x;
    int warp = tid >> 5;
    int wm = (warp & 1) * 64;      // m offset
    int wn = (warp >> 1) * 32;     // c' offset
    const float* ab = g_vbuf + (size_t)b * DD * NN;

    wmma::fragment<wmma::accumulator, 16, 16, 8, float> acc[4][2];
#pragma unroll
    for (int i = 0; i < 4; i++)
#pragma unroll
        for (int j = 0; j < 2; j++) wmma::fill_fragment(acc[i][j], 0.0f);

    int ld[4], lm4[4];
#pragma unroll
    for (int i = 0; i < 4; i++) {
        int f = tid + 256 * i;
        ld[i] = f >> 5;  lm4[i] = f & 31;
    }

#define LOAD_O_TILE(kt, buf) do {                                              \
        float* As_ = smo + (buf) * STG_O;                                      \
        float* Bs_ = As_ + AO_F;                                               \
        int k0_ = (kt) * BKX;                                                  \
        _Pragma("unroll")                                                      \
        for (int i = 0; i < 4; i++) {                                          \
            cp_async16(&As_[ld[i] * LDAX + lm4[i] * 4],                        \
                       ab + (size_t)(k0_ + ld[i]) * NN + m0 + lm4[i] * 4);     \
            cp_async16(&Bs_[ld[i] * LDAX + lm4[i] * 4],                        \
                       wo + (size_t)(k0_ + ld[i]) * DD + c0 + lm4[i] * 4);     \
        }                                                                      \
        cp_commit();                                                           \
    } while (0)

    LOAD_O_TILE(0, 0);
    for (int kt = 0; kt < DD / BKX; kt++) {
        int buf = kt & 1;
        if (kt + 1 < DD / BKX) { LOAD_O_TILE(kt + 1, buf ^ 1); cp_wait1(); }
        else cp_wait0();
        __syncthreads();
        float* As_ = smo + buf * STG_O;
        float* Bs_ = As_ + AO_F;
#pragma unroll
        for (int kk = 0; kk < BKX; kk += 8) {
            wmma::fragment<wmma::matrix_a, 16, 16, 8, wmma::precision::tf32, wmma::col_major> af[4];
            wmma::fragment<wmma::matrix_b, 16, 16, 8, wmma::precision::tf32, wmma::row_major> bf[2];
#pragma unroll
            for (int i = 0; i < 4; i++) {
                wmma::load_matrix_sync(af[i], As_ + kk * LDAX + wm + 16 * i, LDAX);
#pragma unroll
                for (int t = 0; t < af[i].num_elements; t++)
                    af[i].x[t] = wmma::__float_to_tf32(af[i].x[t]);
            }
#pragma unroll
            for (int j = 0; j < 2; j++) {
                wmma::load_matrix_sync(bf[j], Bs_ + kk * LDAX + wn + 16 * j, LDAX);
#pragma unroll
                for (int t = 0; t < bf[j].num_elements; t++)
                    bf[j].x[t] = wmma::__float_to_tf32(bf[j].x[t]);
            }
#pragma unroll
            for (int i = 0; i < 4; i++)
#pragma unroll
                for (int j = 0; j < 2; j++)
                    wmma::mma_sync(acc[i][j], af[i], bf[j], acc[i][j]);
        }
        __syncthreads();
    }
#pragma unroll
    for (int i = 0; i < 4; i++)
#pragma unroll
        for (int j = 0; j < 2; j++) {
            float* cp = outp + ((size_t)b * NN + m0 + wm + 16 * i) * DD + c0 + wn + 16 * j;
            wmma::store_matrix_sync(cp, acc[i][j], DD, wmma::mem_row_major);
        }
}

// ---------------- 6) FFT -> *g -> IFFT -> fused butterfly/scale/residual ----------------
__global__ void k_fft() {
    extern __shared__ float2 sm[];
    float2* d = sm;              // 8192 complex
    float2* tw = sm + 8192;      // 4096 twiddles
    int tid = threadIdx.x;
    int seq = blockIdx.x;
    int row = seq >> 6;
    float* base = g_vbuf + (size_t)seq * NN;

    for (int t = tid; t < 4096; t += 256) {
        float sv, cv;
        sincospif(t * (1.0f / 4096.0f), &sv, &cv);
        tw[t] = make_float2(cv, -sv);
    }
    for (int n = tid; n < NN; n += 256) d[n] = make_float2(base[n], 0.f);
    __syncthreads();

    int shift = 0;
    for (int m = 4096; m >= 1; m >>= 1) {
        for (int idx = tid; idx < 4096; idx += 256) {
            int j = idx & (m - 1);
            int bas = ((idx - j) << 1) + j;
            float2 a = d[bas];
            float2 b2 = d[bas + m];
            float2 w = tw[j << shift];
            float dx = a.x - b2.x, dy = a.y - b2.y;
            d[bas] = make_float2(a.x + b2.x, a.y + b2.y);
            d[bas + m] = make_float2(dx * w.x - dy * w.y, dx * w.y + dy * w.x);
        }
        shift++;
        __syncthreads();
    }

    const float* gre = g_gbuf + (size_t)row * (2 * NN);
    const float* gim = gre + NN;
    for (int p = tid; p < NN; p += 256) {
        int k = __brev((unsigned)p) >> 19;
        float2 a = d[p];
        float gr = gre[k], gi = gim[k];
        d[p] = make_float2(a.x * gr - a.y * gi, a.x * gi + a.y * gr);
    }
    __syncthreads();

    shift = 12;
    for (int m = 1; m <= 4096; m <<= 1) {
        for (int idx = tid; idx < 4096; idx += 256) {
            int j = idx & (m - 1);
            int bas = ((idx - j) << 1) + j;
            float2 a = d[bas];
            float2 b2 = d[bas + m];
            float2 w = tw[j << shift];
            float tx2 = b2.x * w.x + b2.y * w.y;
            float ty2 = b2.y * w.x - b2.x * w.y;
            d[bas] = make_float2(a.x + tx2, a.y + ty2);
            d[bas + m] = make_float2(a.x - tx2, a.y - ty2);
        }
        shift--;
        __syncthreads();
    }

    const float* srow = g_sbuf + (size_t)row * NN;
    const float inv = 1.0f / (float)NN;
    for (int k = tid; k < NN / 2; k += 256) {
        float e = d[2 * k].x * inv;
        float o = d[2 * k + 1].x * inv;
        float s0 = srow[k];
        float s1 = srow[NN / 2 + k];
        float su = e + o, df = e - o;
        float p = s0 * su, q = s1 * df;
        base[2 * k] = e + 0.5f * (p + q);
        base[2 * k + 1] = o + 0.5f * (p - q);
    }
}

// ---------------- launch ----------------
extern "C" void kernel_launch(void* const* d_in, const int* in_sizes, int n_in,
                              void* d_out, int out_size) {
    const float* x       = (const float*)d_in[0];
    const float* w_q     = (const float*)d_in[1];
    const float* w_v     = (const float*)d_in[2];
    const float* w_o     = (const float*)d_in[3];
    const float* ln_g    = (const float*)d_in[4];
    const float* ln_b    = (const float*)d_in[5];
    const float* gate_w1 = (const float*)d_in[6];
    const float* gate_w2 = (const float*)d_in[7];
    const float* wrm_w1  = (const float*)d_in[8];
    const float* wrm_w2  = (const float*)d_in[9];
    float* outp = (float*)d_out;

    cudaFuncSetAttribute(k_fft, cudaFuncAttributeMaxDynamicSharedMemorySize, 96 * 1024);
    cudaFuncSetAttribute(k_gemm_v_tc, cudaFuncAttributeMaxDynamicSharedMemorySize, 2 * STG_V * 4);
    cudaFuncSetAttribute(k_gemm_o_tc, cudaFuncAttributeMaxDynamicSharedMemorySize, 2 * STG_O * 4);

    k_xbar_part<<<dim3(NSPLIT, BB), 256>>>(x);
    k_xbar_red<<<BB, 256>>>();
    k_barq<<<dim3(DD / 256, BB), 256>>>(w_q);
    k_ln_mlp<<<ROWS, 256>>>(ln_g, ln_b, gate_w1, wrm_w1);
    k_gs<<<dim3(2 * NN / 256, 4), 256>>>(gate_w2, 2 * NN, 0);
    k_gs<<<dim3(NN / 256, 4), 256>>>(wrm_w2, NN, 1);
    k_gemm_v_tc<<<dim3(DD / 128, NN / 128, BB), 256, 2 * STG_V * 4>>>(x, w_v);
    k_fft<<<BB * DD, 256, 96 * 1024>>>();
    k_gemm_o_tc<<<dim3(DD / 128, NN / 128, BB), 256, 2 * STG_O * 4>>>(w_o, outp);
}

// round 7
// speedup vs baseline: 1.2675x; 1.2675x over previous
#include <cuda_runtime.h>
#include <mma.h>
#include <math.h>

using namespace nvcuda;

// Problem constants
#define BB 4
#define NN 8192
#define DD 1024
#define HH 16
#define DHH 64
#define GHH 256
#define ROWS (BB*HH)          // 64
#define NSPLIT 64

// ---------------- scratch (static device allocations only) ----------------
__device__ float g_part[NSPLIT * BB * DD];
__device__ float g_xbar[BB * DD];
__device__ float g_barq[BB * DD];
__device__ float g_h1[ROWS * GHH];
__device__ float g_h2[ROWS * GHH];
__device__ float g_gbuf[ROWS * 2 * NN];             // re | im
__device__ float g_sbuf[ROWS * NN];
__device__ float g_vbuf[(size_t)BB * DD * NN];      // [b][c][n]

__device__ __forceinline__ float gelu_exact(float x) {
    return 0.5f * x * (1.0f + erff(x * 0.70710678118654752440f));
}

// -------- cp.async helpers --------
__device__ __forceinline__ void cp_async16(void* smem_dst, const void* gmem_src) {
    unsigned s = (unsigned)__cvta_generic_to_shared(smem_dst);
    asm volatile("cp.async.cg.shared.global [%0], [%1], 16;\n" :: "r"(s), "l"(gmem_src));
}
__device__ __forceinline__ void cp_commit() { asm volatile("cp.async.commit_group;\n"); }
__device__ __forceinline__ void cp_wait1()  { asm volatile("cp.async.wait_group 1;\n"); }
__device__ __forceinline__ void cp_wait0()  { asm volatile("cp.async.wait_group 0;\n"); }

// ---------------- 1) xbar = mean_n x ----------------
__global__ void k_xbar_part(const float* __restrict__ x) {
    int s = blockIdx.x, b = blockIdx.y, tid = threadIdx.x;
    float acc[4] = {0.f, 0.f, 0.f, 0.f};
    const float* xp = x + ((size_t)b * NN + (size_t)s * (NN / NSPLIT)) * DD;
    for (int n = 0; n < NN / NSPLIT; n++) {
#pragma unroll
        for (int i = 0; i < 4; i++) acc[i] += xp[(size_t)n * DD + tid + 256 * i];
    }
#pragma unroll
    for (int i = 0; i < 4; i++)
        g_part[((size_t)s * BB + b) * DD + tid + 256 * i] = acc[i];
}

__global__ void k_xbar_red() {
    int b = blockIdx.x, tid = threadIdx.x;
    for (int d = tid; d < DD; d += 256) {
        float a = 0.f;
        for (int s = 0; s < NSPLIT; s++) a += g_part[((size_t)s * BB + b) * DD + d];
        g_xbar[b * DD + d] = a * (1.0f / NN);
    }
}

// ---------------- 2) bar_q = xbar @ w_q ----------------
__global__ void k_barq(const float* __restrict__ wq) {
    __shared__ float xb[DD];
    int b = blockIdx.y, tid = threadIdx.x;
    for (int l = tid; l < DD; l += 256) xb[l] = g_xbar[b * DD + l];
    __syncthreads();
    int c = blockIdx.x * 256 + tid;
    float acc = 0.f;
    for (int d = 0; d < DD; d++) acc += xb[d] * wq[(size_t)d * DD + c];
    g_barq[b * DD + c] = acc;
}

// ---------------- 3) LayerNorm + tiny MLP first layers ----------------
__global__ void k_ln_mlp(const float* __restrict__ ln_g, const float* __restrict__ ln_b,
                         const float* __restrict__ gate_w1, const float* __restrict__ wrm_w1) {
    __shared__ float q[DHH];
    __shared__ float qn[DHH];
    __shared__ float stats[2];
    int r = blockIdx.x;
    int b = r / HH, c0 = (r % HH) * DHH;
    int tid = threadIdx.x;
    if (tid < DHH) q[tid] = g_barq[b * DD + c0 + tid];
    __syncthreads();
    if (tid == 0) {
        float mu = 0.f;
        for (int i = 0; i < DHH; i++) mu += q[i];
        mu *= (1.0f / DHH);
        float var = 0.f;
        for (int i = 0; i < DHH; i++) { float t = q[i] - mu; var += t * t; }
        var *= (1.0f / DHH);
        stats[0] = mu; stats[1] = rsqrtf(var + 1e-5f);
    }
    __syncthreads();
    if (tid < DHH) qn[tid] = (q[tid] - stats[0]) * stats[1] * ln_g[tid] + ln_b[tid];
    __syncthreads();
    float a1 = 0.f, a2 = 0.f;
    for (int dh = 0; dh < DHH; dh++) {
        float qv = qn[dh];
        a1 += qv * gate_w1[dh * GHH + tid];
        a2 += qv * wrm_w1[dh * GHH + tid];
    }
    g_h1[r * GHH + tid] = gelu_exact(a1);
    g_h2[r * GHH + tid] = gelu_exact(a2);
}

// ---------------- 4) g = h1 @ gate_w2 ; s = h2 @ wrm_w2 ----------------
__global__ void k_gs(const float* __restrict__ w2, int width, int which) {
    __shared__ float sh[16][GHH];
    const float* hb = which ? g_h2 : g_h1;
    float* op = which ? g_sbuf : g_gbuf;
    int r0 = blockIdx.y * 16;
    int tid = threadIdx.x;
    for (int l = tid; l < 16 * GHH; l += 256)
        sh[l >> 8][l & 255] = hb[(r0 + (l >> 8)) * GHH + (l & 255)];
    __syncthreads();
    int c = blockIdx.x * 256 + tid;
    float acc[16];
#pragma unroll
    for (int r = 0; r < 16; r++) acc[r] = 0.f;
    for (int j = 0; j < GHH; j++) {
        float w = w2[(size_t)j * width + c];
#pragma unroll
        for (int r = 0; r < 16; r++) acc[r] += sh[r][j] * w;
    }
#pragma unroll
    for (int r = 0; r < 16; r++) op[(size_t)(r0 + r) * width + c] = acc[r];
}

// ================= tf32 GEMMs: 128x256 tile, warp 64x64, BK=32 =================
#define BKX 32
#define LDA_ 132               // pad for 128-wide m tiles
#define LDBV 36                // v-GEMM B: [n][d], 32 d + pad
#define LDBO 260               // o-GEMM B: [d][c'], 256 c' + pad
#define LDC_ 264               // epilogue staging ld

#define AV_F (BKX * LDA_)      // 4224
#define BV_F (256 * LDBV)      // 9216
#define STG_V (AV_F + BV_F)    // 13440 fl -> 2 stages 107,520 B
#define AO_F (BKX * LDA_)      // 4224
#define BO_F (BKX * LDBO)      // 8320
#define STG_O (AO_F + BO_F)    // 12544 fl -> 2 stages 100,352 B

// ---------------- 5) v = x @ w_v -> g_vbuf[b][c][n] ----------------
// C[c (128)][n (256)] = sum_d wv[d][c] * x[n][d]
__global__ __launch_bounds__(256) void k_gemm_v_tc(const float* __restrict__ x,
                                                   const float* __restrict__ wv) {
    extern __shared__ __align__(16) float smv[];
    int b = blockIdx.z;
    int c0 = blockIdx.x * 128;     // c-tile fastest: 8 CTAs share x n-block in L2
    int n0 = blockIdx.y * 256;
    int tid = threadIdx.x;
    int warp = tid >> 5;
    int wm = (warp & 1) * 64;      // c offset
    int wn = (warp >> 1) * 64;     // n offset
    const float* xb = x + (size_t)b * NN * DD;

    wmma::fragment<wmma::accumulator, 16, 16, 8, float> acc[4][4];
#pragma unroll
    for (int i = 0; i < 4; i++)
#pragma unroll
        for (int j = 0; j < 4; j++) wmma::fill_fragment(acc[i][j], 0.0f);

#define LOAD_V_TILE(kt, buf) do {                                              \
        float* As_ = smv + (buf) * STG_V;                                      \
        float* Bs_ = As_ + AV_F;                                               \
        int k0_ = (kt) * BKX;                                                  \
        _Pragma("unroll")                                                      \
        for (int i = 0; i < 4; i++) {                                          \
            int f = tid + 256 * i; int dd_ = f >> 5, c4 = f & 31;              \
            cp_async16(&As_[dd_ * LDA_ + c4 * 4],                              \
                       wv + (size_t)(k0_ + dd_) * DD + c0 + c4 * 4);           \
        }                                                                      \
        _Pragma("unroll")                                                      \
        for (int i = 0; i < 8; i++) {                                          \
            int f = tid + 256 * i; int n_ = f >> 3, d4 = f & 7;                \
            cp_async16(&Bs_[n_ * LDBV + d4 * 4],                               \
                       xb + (size_t)(n0 + n_) * DD + k0_ + d4 * 4);            \
        }                                                                      \
        cp_commit();                                                           \
    } while (0)

    LOAD_V_TILE(0, 0);
    for (int kt = 0; kt < DD / BKX; kt++) {
        int buf = kt & 1;
        if (kt + 1 < DD / BKX) { LOAD_V_TILE(kt + 1, buf ^ 1); cp_wait1(); }
        else cp_wait0();
        __syncthreads();
        float* As_ = smv + buf * STG_V;
        float* Bs_ = As_ + AV_F;
#pragma unroll
        for (int kk = 0; kk < BKX; kk += 8) {
            wmma::fragment<wmma::matrix_a, 16, 16, 8, wmma::precision::tf32, wmma::col_major> af[4];
            wmma::fragment<wmma::matrix_b, 16, 16, 8, wmma::precision::tf32, wmma::col_major> bf[4];
#pragma unroll
            for (int i = 0; i < 4; i++) {
                wmma::load_matrix_sync(af[i], As_ + kk * LDA_ + wm + 16 * i, LDA_);
#pragma unroll
                for (int t = 0; t < af[i].num_elements; t++)
                    af[i].x[t] = wmma::__float_to_tf32(af[i].x[t]);
            }
#pragma unroll
            for (int j = 0; j < 4; j++) {
                wmma::load_matrix_sync(bf[j], Bs_ + (wn + 16 * j) * LDBV + kk, LDBV);
#pragma unroll
                for (int t = 0; t < bf[j].num_elements; t++)
                    bf[j].x[t] = wmma::__float_to_tf32(bf[j].x[t]);
            }
#pragma unroll
            for (int i = 0; i < 4; i++)
#pragma unroll
                for (int j = 0; j < 4; j++)
                    wmma::mma_sync(acc[i][j], af[i], bf[j], acc[i][j]);
        }
        __syncthreads();
    }

    // smem-staged coalesced epilogue: 4 chunks of 32 c-rows
    float* cs = smv;
#pragma unroll
    for (int ch = 0; ch < 4; ch++) {
        int base = ch * 32;
#pragma unroll
        for (int i = 0; i < 4; i++) {
            int row = wm + 16 * i;
            if (row >= base && row < base + 32) {
#pragma unroll
                for (int j = 0; j < 4; j++)
                    wmma::store_matrix_sync(&cs[(row - base) * LDC_ + wn + 16 * j],
                                            acc[i][j], LDC_, wmma::mem_row_major);
            }
        }
        __syncthreads();
#pragma unroll
        for (int f = tid; f < 32 * 64; f += 256) {
            int r = f >> 6, qq = f & 63;
            float4 val = *(float4*)&cs[r * LDC_ + qq * 4];
            *(float4*)(g_vbuf + ((size_t)b * DD + c0 + base + r) * NN + n0 + qq * 4) = val;
        }
        __syncthreads();
    }
}

// ---------------- 7) out = y @ w_o  (y[b][m][d] = g_vbuf[b][d][m]) ----------------
// C[m (128)][c' (256)] = sum_d vbuf[d][m] * wo[d][c']
__global__ __launch_bounds__(256) void k_gemm_o_tc(const float* __restrict__ wo,
                                                   float* __restrict__ outp) {
    extern __shared__ __align__(16) float smo[];
    int b = blockIdx.z;
    int c0 = blockIdx.x * 256;     // c'-tile fastest: 4 CTAs share vbuf m-block
    int m0 = blockIdx.y * 128;
    int tid = threadIdx.x;
    int warp = tid >> 5;
    int wm = (warp & 1) * 64;      // m offset
    int wn = (warp >> 1) * 64;     // c' offset
    const float* ab = g_vbuf + (size_t)b * DD * NN;

    wmma::fragment<wmma::accumulator, 16, 16, 8, float> acc[4][4];
#pragma unroll
    for (int i = 0; i < 4; i++)
#pragma unroll
        for (int j = 0; j < 4; j++) wmma::fill_fragment(acc[i][j], 0.0f);

#define LOAD_O_TILE(kt, buf) do {                                              \
        float* As_ = smo + (buf) * STG_O;                                      \
        float* Bs_ = As_ + AO_F;                                               \
        int k0_ = (kt) * BKX;                                                  \
        _Pragma("unroll")                                                      \
        for (int i = 0; i < 4; i++) {                                          \
            int f = tid + 256 * i; int dd_ = f >> 5, m4 = f & 31;              \
            cp_async16(&As_[dd_ * LDA_ + m4 * 4],                              \
                       ab + (size_t)(k0_ + dd_) * NN + m0 + m4 * 4);           \
        }                                                                      \
        _Pragma("unroll")                                                      \
        for (int i = 0; i < 8; i++) {                                          \
            int f = tid + 256 * i; int dd_ = f >> 6, c4 = f & 63;              \
            cp_async16(&Bs_[dd_ * LDBO + c4 * 4],                              \
                       wo + (size_t)(k0_ + dd_) * DD + c0 + c4 * 4);           \
        }                                                                      \
        cp_commit();                                                           \
    } while (0)

    LOAD_O_TILE(0, 0);
    for (int kt = 0; kt < DD / BKX; kt++) {
        int buf = kt & 1;
        if (kt + 1 < DD / BKX) { LOAD_O_TILE(kt + 1, buf ^ 1); cp_wait1(); }
        else cp_wait0();
        __syncthreads();
        float* As_ = smo + buf * STG_O;
        float* Bs_ = As_ + AO_F;
#pragma unroll
        for (int kk = 0; kk < BKX; kk += 8) {
            wmma::fragment<wmma::matrix_a, 16, 16, 8, wmma::precision::tf32, wmma::col_major> af[4];
            wmma::fragment<wmma::matrix_b, 16, 16, 8, wmma::precision::tf32, wmma::row_major> bf[4];
#pragma unroll
            for (int i = 0; i < 4; i++) {
                wmma::load_matrix_sync(af[i], As_ + kk * LDA_ + wm + 16 * i, LDA_);
#pragma unroll
                for (int t = 0; t < af[i].num_elements; t++)
                    af[i].x[t] = wmma::__float_to_tf32(af[i].x[t]);
            }
#pragma unroll
            for (int j = 0; j < 4; j++) {
                wmma::load_matrix_sync(bf[j], Bs_ + kk * LDBO + wn + 16 * j, LDBO);
#pragma unroll
                for (int t = 0; t < bf[j].num_elements; t++)
                    bf[j].x[t] = wmma::__float_to_tf32(bf[j].x[t]);
            }
#pragma unroll
            for (int i = 0; i < 4; i++)
#pragma unroll
                for (int j = 0; j < 4; j++)
                    wmma::mma_sync(acc[i][j], af[i], bf[j], acc[i][j]);
        }
        __syncthreads();
    }

    // smem-staged coalesced epilogue
    float* cs = smo;
#pragma unroll
    for (int ch = 0; ch < 4; ch++) {
        int base = ch * 32;
#pragma unroll
        for (int i = 0; i < 4; i++) {
            int row = wm + 16 * i;
            if (row >= base && row < base + 32) {
#pragma unroll
                for (int j = 0; j < 4; j++)
                    wmma::store_matrix_sync(&cs[(row - base) * LDC_ + wn + 16 * j],
                                            acc[i][j], LDC_, wmma::mem_row_major);
            }
        }
        __syncthreads();
#pragma unroll
        for (int f = tid; f < 32 * 64; f += 256) {
            int r = f >> 6, qq = f & 63;
            float4 val = *(float4*)&cs[r * LDC_ + qq * 4];
            *(float4*)(outp + ((size_t)b * NN + m0 + base + r) * DD + c0 + qq * 4) = val;
        }
        __syncthreads();
    }
}

// ---------------- 6) FFT (radix-4 composite) -> *g -> IFFT -> fused epilogue ------
// Each composite butterfly == exact composition of two radix-2 DIF/DIT stages,
// so the overall permutation stays 13-bit bit-reversal and twiddles are identical.
__global__ void k_fft() {
    extern __shared__ float2 sm[];
    float2* d = sm;              // 8192 complex
    float2* tw = sm + 8192;      // tw[t] = exp(-i*pi*t/4096)
    int tid = threadIdx.x;
    int seq = blockIdx.x;
    int row = seq >> 6;
    float* base = g_vbuf + (size_t)seq * NN;

    for (int t = tid; t < 4096; t += 512) {
        float sv, cv;
        sincospif(t * (1.0f / 4096.0f), &sv, &cv);
        tw[t] = make_float2(cv, -sv);
    }
    for (int n = tid; n < NN; n += 512) d[n] = make_float2(base[n], 0.f);
    __syncthreads();

    // ---- forward: 6 composite radix-4 stages (m,m/2), then radix-2 m=1 ----
    for (int m = 4096, s = 0; m >= 4; m >>= 2, s += 2) {
        int q = m >> 1;
        for (int idx = tid; idx < 2048; idx += 512) {
            int j = idx & (q - 1);
            int bas = ((idx - j) << 2) + j;
            float2 x0 = d[bas], x1 = d[bas + q], x2 = d[bas + m], x3 = d[bas + m + q];
            float2 w1 = tw[j << s];
            float2 w2 = tw[j << (s + 1)];
            float2 y0 = make_float2(x0.x + x2.x, x0.y + x2.y);
            float2 y1 = make_float2(x1.x + x3.x, x1.y + x3.y);
            float2 d0 = make_float2(x0.x - x2.x, x0.y - x2.y);
            float2 d1 = make_float2(x1.x - x3.x, x1.y - x3.y);
            // out0 = y0+y1 ; out1 = (y0-y1)*w2
            d[bas] = make_float2(y0.x + y1.x, y0.y + y1.y);
            float2 s1 = make_float2(y0.x - y1.x, y0.y - y1.y);
            d[bas + q] = make_float2(s1.x * w2.x - s1.y * w2.y, s1.x * w2.y + s1.y * w2.x);
            // u = d0*w1 ; v = d1*w1 ; y3 = -i*v
            float2 u = make_float2(d0.x * w1.x - d0.y * w1.y, d0.x * w1.y + d0.y * w1.x);
            float2 v = make_float2(d1.x * w1.x - d1.y * w1.y, d1.x * w1.y + d1.y * w1.x);
            float2 y3 = make_float2(v.y, -v.x);
            d[bas + m] = make_float2(u.x + y3.x, u.y + y3.y);
            float2 s3 = make_float2(u.x - y3.x, u.y - y3.y);
            d[bas + m + q] = make_float2(s3.x * w2.x - s3.y * w2.y, s3.x * w2.y + s3.y * w2.x);
        }
        __syncthreads();
    }
    // final radix-2 stage m=1 (w = 1)
    for (int i = tid; i < 4096; i += 512) {
        float2 a = d[2 * i], b2 = d[2 * i + 1];
        d[2 * i] = make_float2(a.x + b2.x, a.y + b2.y);
        d[2 * i + 1] = make_float2(a.x - b2.x, a.y - b2.y);
    }
    __syncthreads();

    // pointwise multiply by g (bit-reversed index)
    const float* gre = g_gbuf + (size_t)row * (2 * NN);
    const float* gim = gre + NN;
    for (int p = tid; p < NN; p += 512) {
        int k = __brev((unsigned)p) >> 19;
        float2 a = d[p];
        float gr = gre[k], gi = gim[k];
        d[p] = make_float2(a.x * gr - a.y * gi, a.x * gi + a.y * gr);
    }
    __syncthreads();

    // ---- inverse: radix-2 m=1, then 6 composite radix-4 stages ascending ----
    for (int i = tid; i < 4096; i += 512) {
        float2 a = d[2 * i], b2 = d[2 * i + 1];
        d[2 * i] = make_float2(a.x + b2.x, a.y + b2.y);
        d[2 * i + 1] = make_float2(a.x - b2.x, a.y - b2.y);
    }
    __syncthreads();
    for (int m = 4, s = 10; m <= 4096; m <<= 2, s -= 2) {
        int q = m >> 1;
        for (int idx = tid; idx < 2048; idx += 512) {
            int j = idx & (q - 1);
            int bas = ((idx - j) << 2) + j;
            float2 z0 = d[bas], z1 = d[bas + q], z2 = d[bas + m], z3 = d[bas + m + q];
            float2 w1 = tw[j << s];          // use conj
            float2 w2 = tw[j << (s + 1)];    // use conj
            // invert stage2 (twiddle w2): t = z*conj(w2)
            float2 t0 = make_float2(z1.x * w2.x + z1.y * w2.y, z1.y * w2.x - z1.x * w2.y);
            float2 t1 = make_float2(z3.x * w2.x + z3.y * w2.y, z3.y * w2.x - z3.x * w2.y);
            float2 A0 = make_float2(z0.x + t0.x, z0.y + t0.y);
            float2 A1 = make_float2(z0.x - t0.x, z0.y - t0.y);
            float2 A2 = make_float2(z2.x + t1.x, z2.y + t1.y);
            float2 A3 = make_float2(z2.x - t1.x, z2.y - t1.y);
            // invert stage1: u = A2*conj(w1); tp = i*(A3*conj(w1))
            float2 u = make_float2(A2.x * w1.x + A2.y * w1.y, A2.y * w1.x - A2.x * w1.y);
            float2 v = make_float2(A3.x * w1.x + A3.y * w1.y, A3.y * w1.x - A3.x * w1.y);
            float2 tp = make_float2(-v.y, v.x);
            d[bas]         = make_float2(A0.x + u.x, A0.y + u.y);
            d[bas + m]     = make_float2(A0.x - u.x, A0.y - u.y);
            d[bas + q]     = make_float2(A1.x + tp.x, A1.y + tp.y);
            d[bas + m + q] = make_float2(A1.x - tp.x, A1.y - tp.y);
        }
        __syncthreads();
    }

    // fused: v_tilde = real/N ; hadamard, scale by s, inverse hadamard, residual add
    const float* srow = g_sbuf + (size_t)row * NN;
    const float inv = 1.0f / (float)NN;
    for (int k = tid; k < NN / 2; k += 512) {
        float e = d[2 * k].x * inv;
        float o = d[2 * k + 1].x * inv;
        float s0 = srow[k];
        float s1v = srow[NN / 2 + k];
        float su = e + o, df = e - o;
        float p = s0 * su, qv = s1v * df;
        base[2 * k] = e + 0.5f * (p + qv);
        base[2 * k + 1] = o + 0.5f * (p - qv);
    }
}

// ---------------- launch ----------------
extern "C" void kernel_launch(void* const* d_in, const int* in_sizes, int n_in,
                              void* d_out, int out_size) {
    const float* x       = (const float*)d_in[0];
    const float* w_q     = (const float*)d_in[1];
    const float* w_v     = (const float*)d_in[2];
    const float* w_o     = (const float*)d_in[3];
    const float* ln_g    = (const float*)d_in[4];
    const float* ln_b    = (const float*)d_in[5];
    const float* gate_w1 = (const float*)d_in[6];
    const float* gate_w2 = (const float*)d_in[7];
    const float* wrm_w1  = (const float*)d_in[8];
    const float* wrm_w2  = (const float*)d_in[9];
    float* outp = (float*)d_out;

    cudaFuncSetAttribute(k_fft, cudaFuncAttributeMaxDynamicSharedMemorySize, 96 * 1024);
    cudaFuncSetAttribute(k_gemm_v_tc, cudaFuncAttributeMaxDynamicSharedMemorySize, 2 * STG_V * 4);
    cudaFuncSetAttribute(k_gemm_o_tc, cudaFuncAttributeMaxDynamicSharedMemorySize, 2 * STG_O * 4);

    k_xbar_part<<<dim3(NSPLIT, BB), 256>>>(x);
    k_xbar_red<<<BB, 256>>>();
    k_barq<<<dim3(DD / 256, BB), 256>>>(w_q);
    k_ln_mlp<<<ROWS, 256>>>(ln_g, ln_b, gate_w1, wrm_w1);
    k_gs<<<dim3(2 * NN / 256, 4), 256>>>(gate_w2, 2 * NN, 0);
    k_gs<<<dim3(NN / 256, 4), 256>>>(wrm_w2, NN, 1);
    k_gemm_v_tc<<<dim3(DD / 128, NN / 256, BB), 256, 2 * STG_V * 4>>>(x, w_v);
    k_fft<<<BB * DD, 512, 96 * 1024>>>();
    k_gemm_o_tc<<<dim3(DD / 256, NN / 128, BB), 256, 2 * STG_O * 4>>>(w_o, outp);
}

// round 15
// speedup vs baseline: 1.2698x; 1.0018x over previous
#include <cuda_runtime.h>
#include <mma.h>
#include <math.h>

using namespace nvcuda;

// Problem constants
#define BB 4
#define NN 8192
#define DD 1024
#define HH 16
#define DHH 64
#define GHH 256
#define ROWS (BB*HH)          // 64
#define NSPLIT 64

// ---------------- scratch (static device allocations only) ----------------
__device__ float g_part[NSPLIT * BB * DD];
__device__ float g_xbar[BB * DD];
__device__ float g_barq[BB * DD];
__device__ float g_h1[ROWS * GHH];
__device__ float g_h2[ROWS * GHH];
__device__ float g_gbuf[ROWS * 2 * NN];             // re | im
__device__ float g_sbuf[ROWS * NN];
__device__ float g_vbuf[(size_t)BB * DD * NN];      // [b][c][n]
__device__ float g_xr[(size_t)BB * NN * DD];        // x pre-rounded to tf32
__device__ float g_wvr[DD * DD];                    // w_v tf32-rounded
__device__ float g_wor[DD * DD];                    // w_o tf32-rounded

__device__ __forceinline__ float gelu_exact(float x) {
    return 0.5f * x * (1.0f + erff(x * 0.70710678118654752440f));
}

// -------- cp.async helpers --------
__device__ __forceinline__ void cp_async16(void* smem_dst, const void* gmem_src) {
    unsigned s = (unsigned)__cvta_generic_to_shared(smem_dst);
    asm volatile("cp.async.cg.shared.global [%0], [%1], 16;\n" :: "r"(s), "l"(gmem_src));
}
__device__ __forceinline__ void cp_commit() { asm volatile("cp.async.commit_group;\n"); }
__device__ __forceinline__ void cp_wait1()  { asm volatile("cp.async.wait_group 1;\n"); }
__device__ __forceinline__ void cp_wait0()  { asm volatile("cp.async.wait_group 0;\n"); }

// ---------------- 1) xbar = mean_n x ----------------
__global__ void k_xbar_part(const float* __restrict__ x) {
    int s = blockIdx.x, b = blockIdx.y, tid = threadIdx.x;
    float acc[4] = {0.f, 0.f, 0.f, 0.f};
    const float* xp = x + ((size_t)b * NN + (size_t)s * (NN / NSPLIT)) * DD;
    for (int n = 0; n < NN / NSPLIT; n++) {
#pragma unroll
        for (int i = 0; i < 4; i++) acc[i] += xp[(size_t)n * DD + tid + 256 * i];
    }
#pragma unroll
    for (int i = 0; i < 4; i++)
        g_part[((size_t)s * BB + b) * DD + tid + 256 * i] = acc[i];
}

__global__ void k_xbar_red() {
    int b = blockIdx.x, tid = threadIdx.x;
    for (int d = tid; d < DD; d += 256) {
        float a = 0.f;
        for (int s = 0; s < NSPLIT; s++) a += g_part[((size_t)s * BB + b) * DD + d];
        g_xbar[b * DD + d] = a * (1.0f / NN);
    }
}

// ---------------- 2) bar_q = xbar @ w_q ----------------
__global__ void k_barq(const float* __restrict__ wq) {
    __shared__ float xb[DD];
    int b = blockIdx.y, tid = threadIdx.x;
    for (int l = tid; l < DD; l += 256) xb[l] = g_xbar[b * DD + l];
    __syncthreads();
    int c = blockIdx.x * 256 + tid;
    float acc = 0.f;
    for (int d = 0; d < DD; d++) acc += xb[d] * wq[(size_t)d * DD + c];
    g_barq[b * DD + c] = acc;
}

// ---------------- pre-rounding to tf32 ----------------
__global__ void k_round_x(const float* __restrict__ x) {
    size_t i = ((size_t)blockIdx.x * 256 + threadIdx.x) * 4;
    float4 v = *(const float4*)(x + i);
    v.x = wmma::__float_to_tf32(v.x);
    v.y = wmma::__float_to_tf32(v.y);
    v.z = wmma::__float_to_tf32(v.z);
    v.w = wmma::__float_to_tf32(v.w);
    *(float4*)(g_xr + i) = v;
}

__global__ void k_round_w(const float* __restrict__ w, int which) {
    float* dst = which ? g_wor : g_wvr;
    size_t i = ((size_t)blockIdx.x * 256 + threadIdx.x) * 4;
    float4 v = *(const float4*)(w + i);
    v.x = wmma::__float_to_tf32(v.x);
    v.y = wmma::__float_to_tf32(v.y);
    v.z = wmma::__float_to_tf32(v.z);
    v.w = wmma::__float_to_tf32(v.w);
    *(float4*)(dst + i) = v;
}

// ---------------- 3) LayerNorm + tiny MLP first layers ----------------
__global__ void k_ln_mlp(const float* __restrict__ ln_g, const float* __restrict__ ln_b,
                         const float* __restrict__ gate_w1, const float* __restrict__ wrm_w1) {
    __shared__ float q[DHH];
    __shared__ float qn[DHH];
    __shared__ float stats[2];
    int r = blockIdx.x;
    int b = r / HH, c0 = (r % HH) * DHH;
    int tid = threadIdx.x;
    if (tid < DHH) q[tid] = g_barq[b * DD + c0 + tid];
    __syncthreads();
    if (tid == 0) {
        float mu = 0.f;
        for (int i = 0; i < DHH; i++) mu += q[i];
        mu *= (1.0f / DHH);
        float var = 0.f;
        for (int i = 0; i < DHH; i++) { float t = q[i] - mu; var += t * t; }
        var *= (1.0f / DHH);
        stats[0] = mu; stats[1] = rsqrtf(var + 1e-5f);
    }
    __syncthreads();
    if (tid < DHH) qn[tid] = (q[tid] - stats[0]) * stats[1] * ln_g[tid] + ln_b[tid];
    __syncthreads();
    float a1 = 0.f, a2 = 0.f;
    for (int dh = 0; dh < DHH; dh++) {
        float qv = qn[dh];
        a1 += qv * gate_w1[dh * GHH + tid];
        a2 += qv * wrm_w1[dh * GHH + tid];
    }
    g_h1[r * GHH + tid] = gelu_exact(a1);
    g_h2[r * GHH + tid] = gelu_exact(a2);
}

// ---------------- 4) g = h1 @ gate_w2 ; s = h2 @ wrm_w2 ----------------
__global__ void k_gs(const float* __restrict__ w2, int width, int which) {
    __shared__ float sh[16][GHH];
    const float* hb = which ? g_h2 : g_h1;
    float* op = which ? g_sbuf : g_gbuf;
    int r0 = blockIdx.y * 16;
    int tid = threadIdx.x;
    for (int l = tid; l < 16 * GHH; l += 256)
        sh[l >> 8][l & 255] = hb[(r0 + (l >> 8)) * GHH + (l & 255)];
    __syncthreads();
    int c = blockIdx.x * 256 + tid;
    float acc[16];
#pragma unroll
    for (int r = 0; r < 16; r++) acc[r] = 0.f;
    for (int j = 0; j < GHH; j++) {
        float w = w2[(size_t)j * width + c];
#pragma unroll
        for (int r = 0; r < 16; r++) acc[r] += sh[r][j] * w;
    }
#pragma unroll
    for (int r = 0; r < 16; r++) op[(size_t)(r0 + r) * width + c] = acc[r];
}

// ================= tf32 GEMMs: 128x256 tile, warp 64x64, BK=32 =================
// Operands pre-rounded to tf32 (g_xr/g_wvr/g_wor/g_vbuf) -> no cvt in mainloop.
#define BKX 32
#define LDA_ 132               // pad for 128-wide m tiles
#define LDBV 36                // v-GEMM B: [n][d], 32 d + pad
#define LDBO 260               // o-GEMM B: [d][c'], 256 c' + pad
#define LDC_ 264               // epilogue staging ld

#define AV_F (BKX * LDA_)      // 4224
#define BV_F (256 * LDBV)      // 9216
#define STG_V (AV_F + BV_F)    // 13440 fl
#define AO_F (BKX * LDA_)      // 4224
#define BO_F (BKX * LDBO)      // 8320
#define STG_O (AO_F + BO_F)    // 12544 fl

// ---------------- 5) v = x @ w_v -> g_vbuf[b][c][n] ----------------
// C[c (128)][n (256)] = sum_d wvr[d][c] * xr[n][d]   (device globals, no host ptr)
__global__ __launch_bounds__(256) void k_gemm_v_tc() {
    extern __shared__ __align__(16) float smv[];
    const float* __restrict__ wv = g_wvr;
    int b = blockIdx.z;
    int c0 = blockIdx.x * 128;     // c-tile fastest: CTAs share x n-block in L2
    int n0 = blockIdx.y * 256;
    int tid = threadIdx.x;
    int warp = tid >> 5;
    int wm = (warp & 1) * 64;      // c offset
    int wn = (warp >> 1) * 64;     // n offset
    const float* xb = g_xr + (size_t)b * NN * DD;

    wmma::fragment<wmma::accumulator, 16, 16, 8, float> acc[4][4];
#pragma unroll
    for (int i = 0; i < 4; i++)
#pragma unroll
        for (int j = 0; j < 4; j++) wmma::fill_fragment(acc[i][j], 0.0f);

#define LOAD_V_TILE(kt, buf) do {                                              \
        float* As_ = smv + (buf) * STG_V;                                      \
        float* Bs_ = As_ + AV_F;                                               \
        int k0_ = (kt) * BKX;                                                  \
        _Pragma("unroll")                                                      \
        for (int i = 0; i < 4; i++) {                                          \
            int f = tid + 256 * i; int dd_ = f >> 5, c4 = f & 31;              \
            cp_async16(&As_[dd_ * LDA_ + c4 * 4],                              \
                       wv + (size_t)(k0_ + dd_) * DD + c0 + c4 * 4);           \
        }                                                                      \
        _Pragma("unroll")                                                      \
        for (int i = 0; i < 8; i++) {                                          \
            int f = tid + 256 * i; int n_ = f >> 3, d4 = f & 7;                \
            cp_async16(&Bs_[n_ * LDBV + d4 * 4],                               \
                       xb + (size_t)(n0 + n_) * DD + k0_ + d4 * 4);            \
        }                                                                      \
        cp_commit();                                                           \
    } while (0)

    LOAD_V_TILE(0, 0);
    for (int kt = 0; kt < DD / BKX; kt++) {
        int buf = kt & 1;
        if (kt + 1 < DD / BKX) { LOAD_V_TILE(kt + 1, buf ^ 1); cp_wait1(); }
        else cp_wait0();
        __syncthreads();
        float* As_ = smv + buf * STG_V;
        float* Bs_ = As_ + AV_F;
#pragma unroll
        for (int kk = 0; kk < BKX; kk += 8) {
            wmma::fragment<wmma::matrix_a, 16, 16, 8, wmma::precision::tf32, wmma::col_major> af[4];
            wmma::fragment<wmma::matrix_b, 16, 16, 8, wmma::precision::tf32, wmma::col_major> bf[4];
#pragma unroll
            for (int i = 0; i < 4; i++)
                wmma::load_matrix_sync(af[i], As_ + kk * LDA_ + wm + 16 * i, LDA_);
#pragma unroll
            for (int j = 0; j < 4; j++)
                wmma::load_matrix_sync(bf[j], Bs_ + (wn + 16 * j) * LDBV + kk, LDBV);
#pragma unroll
            for (int i = 0; i < 4; i++)
#pragma unroll
                for (int j = 0; j < 4; j++)
                    wmma::mma_sync(acc[i][j], af[i], bf[j], acc[i][j]);
        }
        __syncthreads();
    }

    // smem-staged coalesced epilogue: 4 chunks of 32 c-rows
    float* cs = smv;
#pragma unroll
    for (int ch = 0; ch < 4; ch++) {
        int base = ch * 32;
#pragma unroll
        for (int i = 0; i < 4; i++) {
            int row = wm + 16 * i;
            if (row >= base && row < base + 32) {
#pragma unroll
                for (int j = 0; j < 4; j++)
                    wmma::store_matrix_sync(&cs[(row - base) * LDC_ + wn + 16 * j],
                                            acc[i][j], LDC_, wmma::mem_row_major);
            }
        }
        __syncthreads();
#pragma unroll
        for (int f = tid; f < 32 * 64; f += 256) {
            int r = f >> 6, qq = f & 63;
            float4 val = *(float4*)&cs[r * LDC_ + qq * 4];
            *(float4*)(g_vbuf + ((size_t)b * DD + c0 + base + r) * NN + n0 + qq * 4) = val;
        }
        __syncthreads();
    }
}

// ---------------- 7) out = y @ w_o  (y[b][m][d] = g_vbuf[b][d][m]) ----------------
// C[m (128)][c' (256)] = sum_d vbuf[d][m] * wor[d][c']
__global__ __launch_bounds__(256) void k_gemm_o_tc(float* __restrict__ outp) {
    extern __shared__ __align__(16) float smo[];
    const float* __restrict__ wo = g_wor;
    int b = blockIdx.z;
    int c0 = blockIdx.x * 256;     // c'-tile fastest
    int m0 = blockIdx.y * 128;
    int tid = threadIdx.x;
    int warp = tid >> 5;
    int wm = (warp & 1) * 64;      // m offset
    int wn = (warp >> 1) * 64;     // c' offset
    const float* ab = g_vbuf + (size_t)b * DD * NN;

    wmma::fragment<wmma::accumulator, 16, 16, 8, float> acc[4][4];
#pragma unroll
    for (int i = 0; i < 4; i++)
#pragma unroll
        for (int j = 0; j < 4; j++) wmma::fill_fragment(acc[i][j], 0.0f);

#define LOAD_O_TILE(kt, buf) do {                                              \
        float* As_ = smo + (buf) * STG_O;                                      \
        float* Bs_ = As_ + AO_F;                                               \
        int k0_ = (kt) * BKX;                                                  \
        _Pragma("unroll")                                                      \
        for (int i = 0; i < 4; i++) {                                          \
            int f = tid + 256 * i; int dd_ = f >> 5, m4 = f & 31;              \
            cp_async16(&As_[dd_ * LDA_ + m4 * 4],                              \
                       ab + (size_t)(k0_ + dd_) * NN + m0 + m4 * 4);           \
        }                                                                      \
        _Pragma("unroll")                                                      \
        for (int i = 0; i < 8; i++) {                                          \
            int f = tid + 256 * i; int dd_ = f >> 6, c4 = f & 63;              \
            cp_async16(&Bs_[dd_ * LDBO + c4 * 4],                              \
                       wo + (size_t)(k0_ + dd_) * DD + c0 + c4 * 4);           \
        }                                                                      \
        cp_commit();                                                           \
    } while (0)

    LOAD_O_TILE(0, 0);
    for (int kt = 0; kt < DD / BKX; kt++) {
        int buf = kt & 1;
        if (kt + 1 < DD / BKX) { LOAD_O_TILE(kt + 1, buf ^ 1); cp_wait1(); }
        else cp_wait0();
        __syncthreads();
        float* As_ = smo + buf * STG_O;
        float* Bs_ = As_ + AO_F;
#pragma unroll
        for (int kk = 0; kk < BKX; kk += 8) {
            wmma::fragment<wmma::matrix_a, 16, 16, 8, wmma::precision::tf32, wmma::col_major> af[4];
            wmma::fragment<wmma::matrix_b, 16, 16, 8, wmma::precision::tf32, wmma::row_major> bf[4];
#pragma unroll
            for (int i = 0; i < 4; i++)
                wmma::load_matrix_sync(af[i], As_ + kk * LDA_ + wm + 16 * i, LDA_);
#pragma unroll
            for (int j = 0; j < 4; j++)
                wmma::load_matrix_sync(bf[j], Bs_ + kk * LDBO + wn + 16 * j, LDBO);
#pragma unroll
            for (int i = 0; i < 4; i++)
#pragma unroll
                for (int j = 0; j < 4; j++)
                    wmma::mma_sync(acc[i][j], af[i], bf[j], acc[i][j]);
        }
        __syncthreads();
    }

    // smem-staged coalesced epilogue
    float* cs = smo;
#pragma unroll
    for (int ch = 0; ch < 4; ch++) {
        int base = ch * 32;
#pragma unroll
        for (int i = 0; i < 4; i++) {
            int row = wm + 16 * i;
            if (row >= base && row < base + 32) {
#pragma unroll
                for (int j = 0; j < 4; j++)
                    wmma::store_matrix_sync(&cs[(row - base) * LDC_ + wn + 16 * j],
                                            acc[i][j], LDC_, wmma::mem_row_major);
            }
        }
        __syncthreads();
#pragma unroll
        for (int f = tid; f < 32 * 64; f += 256) {
            int r = f >> 6, qq = f & 63;
            float4 val = *(float4*)&cs[r * LDC_ + qq * 4];
            *(float4*)(outp + ((size_t)b * NN + m0 + base + r) * DD + c0 + qq * 4) = val;
        }
        __syncthreads();
    }
}

// ---------------- 6) FFT (radix-4 composite) -> *g -> IFFT -> fused epilogue ------
// Epilogue stores v_tilde pre-rounded to tf32 so the o-GEMM needs no cvt.
__global__ void k_fft() {
    extern __shared__ float2 sm[];
    float2* d = sm;
    float2* tw = sm + 8192;
    int tid = threadIdx.x;
    int seq = blockIdx.x;
    int row = seq >> 6;
    float* base = g_vbuf + (size_t)seq * NN;

    for (int t = tid; t < 4096; t += 512) {
        float sv, cv;
        sincospif(t * (1.0f / 4096.0f), &sv, &cv);
        tw[t] = make_float2(cv, -sv);
    }
    for (int n = tid; n < NN; n += 512) d[n] = make_float2(base[n], 0.f);
    __syncthreads();

    for (int m = 4096, s = 0; m >= 4; m >>= 2, s += 2) {
        int q = m >> 1;
        for (int idx = tid; idx < 2048; idx += 512) {
            int j = idx & (q - 1);
            int bas = ((idx - j) << 2) + j;
            float2 x0 = d[bas], x1 = d[bas + q], x2 = d[bas + m], x3 = d[bas + m + q];
            float2 w1 = tw[j << s];
            float2 w2 = tw[j << (s + 1)];
            float2 y0 = make_float2(x0.x + x2.x, x0.y + x2.y);
            float2 y1 = make_float2(x1.x + x3.x, x1.y + x3.y);
            float2 d0 = make_float2(x0.x - x2.x, x0.y - x2.y);
            float2 d1 = make_float2(x1.x - x3.x, x1.y - x3.y);
            d[bas] = make_float2(y0.x + y1.x, y0.y + y1.y);
            float2 s1 = make_float2(y0.x - y1.x, y0.y - y1.y);
            d[bas + q] = make_float2(s1.x * w2.x - s1.y * w2.y, s1.x * w2.y + s1.y * w2.x);
            float2 u = make_float2(d0.x * w1.x - d0.y * w1.y, d0.x * w1.y + d0.y * w1.x);
            float2 v = make_float2(d1.x * w1.x - d1.y * w1.y, d1.x * w1.y + d1.y * w1.x);
            float2 y3 = make_float2(v.y, -v.x);
            d[bas + m] = make_float2(u.x + y3.x, u.y + y3.y);
            float2 s3 = make_float2(u.x - y3.x, u.y - y3.y);
            d[bas + m + q] = make_float2(s3.x * w2.x - s3.y * w2.y, s3.x * w2.y + s3.y * w2.x);
        }
        __syncthreads();
    }
    for (int i = tid; i < 4096; i += 512) {
        float2 a = d[2 * i], b2 = d[2 * i + 1];
        d[2 * i] = make_float2(a.x + b2.x, a.y + b2.y);
        d[2 * i + 1] = make_float2(a.x - b2.x, a.y - b2.y);
    }
    __syncthreads();

    const float* gre = g_gbuf + (size_t)row * (2 * NN);
    const float* gim = gre + NN;
    for (int p = tid; p < NN; p += 512) {
        int k = __brev((unsigned)p) >> 19;
        float2 a = d[p];
        float gr = gre[k], gi = gim[k];
        d[p] = make_float2(a.x * gr - a.y * gi, a.x * gi + a.y * gr);
    }
    __syncthreads();

    for (int i = tid; i < 4096; i += 512) {
        float2 a = d[2 * i], b2 = d[2 * i + 1];
        d[2 * i] = make_float2(a.x + b2.x, a.y + b2.y);
        d[2 * i + 1] = make_float2(a.x - b2.x, a.y - b2.y);
    }
    __syncthreads();
    for (int m = 4, s = 10; m <= 4096; m <<= 2, s -= 2) {
        int q = m >> 1;
        for (int idx = tid; idx < 2048; idx += 512) {
            int j = idx & (q - 1);
            int bas = ((idx - j) << 2) + j;
            float2 z0 = d[bas], z1 = d[bas + q], z2 = d[bas + m], z3 = d[bas + m + q];
            float2 w1 = tw[j << s];
            float2 w2 = tw[j << (s + 1)];
            float2 t0 = make_float2(z1.x * w2.x + z1.y * w2.y, z1.y * w2.x - z1.x * w2.y);
            float2 t1 = make_float2(z3.x * w2.x + z3.y * w2.y, z3.y * w2.x - z3.x * w2.y);
            float2 A0 = make_float2(z0.x + t0.x, z0.y + t0.y);
            float2 A1 = make_float2(z0.x - t0.x, z0.y - t0.y);
            float2 A2 = make_float2(z2.x + t1.x, z2.y + t1.y);
            float2 A3 = make_float2(z2.x - t1.x, z2.y - t1.y);
            float2 u = make_float2(A2.x * w1.x + A2.y * w1.y, A2.y * w1.x - A2.x * w1.y);
            float2 v = make_float2(A3.x * w1.x + A3.y * w1.y, A3.y * w1.x - A3.x * w1.y);
            float2 tp = make_float2(-v.y, v.x);
            d[bas]         = make_float2(A0.x + u.x, A0.y + u.y);
            d[bas + m]     = make_float2(A0.x - u.x, A0.y - u.y);
            d[bas + q]     = make_float2(A1.x + tp.x, A1.y + tp.y);
            d[bas + m + q] = make_float2(A1.x - tp.x, A1.y - tp.y);
        }
        __syncthreads();
    }

    const float* srow = g_sbuf + (size_t)row * NN;
    const float inv = 1.0f / (float)NN;
    for (int k = tid; k < NN / 2; k += 512) {
        float e = d[2 * k].x * inv;
        float o = d[2 * k + 1].x * inv;
        float s0 = srow[k];
        float s1v = srow[NN / 2 + k];
        float su = e + o, df = e - o;
        float p = s0 * su, qv = s1v * df;
        base[2 * k] = wmma::__float_to_tf32(e + 0.5f * (p + qv));
        base[2 * k + 1] = wmma::__float_to_tf32(o + 0.5f * (p - qv));
    }
}

// ---------------- launch ----------------
extern "C" void kernel_launch(void* const* d_in, const int* in_sizes, int n_in,
                              void* d_out, int out_size) {
    const float* x       = (const float*)d_in[0];
    const float* w_q     = (const float*)d_in[1];
    const float* w_v     = (const float*)d_in[2];
    const float* w_o     = (const float*)d_in[3];
    const float* ln_g    = (const float*)d_in[4];
    const float* ln_b    = (const float*)d_in[5];
    const float* gate_w1 = (const float*)d_in[6];
    const float* gate_w2 = (const float*)d_in[7];
    const float* wrm_w1  = (const float*)d_in[8];
    const float* wrm_w2  = (const float*)d_in[9];
    float* outp = (float*)d_out;

    cudaFuncSetAttribute(k_fft, cudaFuncAttributeMaxDynamicSharedMemorySize, 96 * 1024);
    cudaFuncSetAttribute(k_gemm_v_tc, cudaFuncAttributeMaxDynamicSharedMemorySize, 2 * STG_V * 4);
    cudaFuncSetAttribute(k_gemm_o_tc, cudaFuncAttributeMaxDynamicSharedMemorySize, 2 * STG_O * 4);

    // Launch order chosen so ncu's fixed window (-s 5 -c 1) captures k_gemm_v_tc.
    k_xbar_part<<<dim3(NSPLIT, BB), 256>>>(x);                                  // 1
    k_xbar_red<<<BB, 256>>>();                                                  // 2
    k_barq<<<dim3(DD / 256, BB), 256>>>(w_q);                                   // 3
    k_round_x<<<(int)(((size_t)BB * NN * DD) / 1024), 256>>>(x);                // 4
    k_round_w<<<(DD * DD) / 1024, 256>>>(w_v, 0);                               // 5
    k_gemm_v_tc<<<dim3(DD / 128, NN / 256, BB), 256, 2 * STG_V * 4>>>();        // 6 (profiled)
    k_round_w<<<(DD * DD) / 1024, 256>>>(w_o, 1);
    k_ln_mlp<<<ROWS, 256>>>(ln_g, ln_b, gate_w1, wrm_w1);
    k_gs<<<dim3(2 * NN / 256, 4), 256>>>(gate_w2, 2 * NN, 0);
    k_gs<<<dim3(NN / 256, 4), 256>>>(wrm_w2, NN, 1);
    k_fft<<<BB * DD, 512, 96 * 1024>>>();
    k_gemm_o_tc<<<dim3(DD / 256, NN / 128, BB), 256, 2 * STG_O * 4>>>(outp);
}